// round 15
// baseline (speedup 1.0000x reference)
#include <cuda_runtime.h>

// y[b,t,c] = (1/(t+1)) * sum_{j<=t} x[b,j,c]   (cumulative mean along T)
// Two-pass, serialization-free:
//   K1: per-(b, 64-row chunk) channel sums -> g_part
//   K2: local register scan + predecessor-partial sum + scaled store
// R14 lesson: pairing chunks raised regs to 80 and dropped occ to 31% (worse).
// Latency-bound -> buy occupancy instead: CHUNK 128->64, RPT 8->4 (16 payload
// regs, ~40 total, 6 CTAs/SM = 75% occ), RL stays 16 (R9: RL=32 is poison).

#define B_      16
#define T_      8192
#define C_      64
#define CHUNK   64
#define NCHUNK  (T_ / CHUNK)          // 128
#define NBLK    (B_ * NCHUNK)         // 2048
#define NTHR    256
#define CG      16                    // float4 channel groups
#define RL      (NTHR / CG)           // 16 row lanes
#define RPT     (CHUNK / RL)          // 4 rows per thread

// Per-chunk channel sums: [b][chunk][c], float4-aligned. 512 KB (L2-resident).
__device__ float4 g_part4[B_ * NCHUNK * CG];

__global__ void __launch_bounds__(NTHR, 8)
k_partial(const float* __restrict__ x) {
    const int bid = blockIdx.x;
    const int b   = bid >> 7;           // /NCHUNK
    const int ch  = bid & (NCHUNK - 1);
    const int tid = threadIdx.x;
    const int cg  = tid & (CG - 1);
    const int rl  = tid >> 4;

    const int row0 = ch * CHUNK + rl * RPT;
    const float4* __restrict__ xp =
        (const float4*)(x + ((size_t)(b * T_ + row0)) * C_ + cg * 4);

    float4 v0 = xp[0 * (C_ / 4)];
    float4 v1 = xp[1 * (C_ / 4)];
    float4 v2 = xp[2 * (C_ / 4)];
    float4 v3 = xp[3 * (C_ / 4)];
    float4 s;
    s.x = (v0.x + v1.x) + (v2.x + v3.x);
    s.y = (v0.y + v1.y) + (v2.y + v3.y);
    s.z = (v0.z + v1.z) + (v2.z + v3.z);
    s.w = (v0.w + v1.w) + (v2.w + v3.w);

    __shared__ float4 red1[RL][CG];
    red1[rl][cg] = s;
    #pragma unroll
    for (int st = RL / 2; st > 0; st >>= 1) {
        __syncthreads();
        if (rl < st) {
            float4 o = red1[rl + st][cg];
            float4 m = red1[rl][cg];
            m.x += o.x; m.y += o.y; m.z += o.z; m.w += o.w;
            red1[rl][cg] = m;
        }
    }
    __syncthreads();
    if (rl == 0)
        g_part4[(b * NCHUNK + ch) * CG + cg] = red1[0][cg];
}

// min-blocks=5 caps at 51 regs (cap only): at ~40 actual regs HW fits 6 CTAs/SM.
__global__ void __launch_bounds__(NTHR, 5)
k_scanout(const float* __restrict__ x, float* __restrict__ y) {
    const int bid = blockIdx.x;
    const int b   = bid >> 7;           // /NCHUNK
    const int ch  = bid & (NCHUNK - 1);
    const int tid = threadIdx.x;
    const int cg  = tid & (CG - 1);
    const int rl  = tid >> 4;           // 0..15

    __shared__ float4 red[RL][CG];
    __shared__ float  pred[4][C_];
    __shared__ float  predt[C_];
    __shared__ float  s_recip[CHUNK];

    // ---- x tile: issue the 4 independent LDG.128 first ----
    const int row0 = ch * CHUNK + rl * RPT;
    const size_t off = ((size_t)(b * T_ + row0)) * C_ + cg * 4;
    const float4* __restrict__ xp = (const float4*)(x + off);

    float4 v0 = xp[0 * (C_ / 4)];
    float4 v1 = xp[1 * (C_ / 4)];
    float4 v2 = xp[2 * (C_ / 4)];
    float4 v3 = xp[3 * (C_ / 4)];

    // Reciprocal table for this chunk's global rows (full-precision divide).
    if (tid < CHUNK)
        s_recip[tid] = 1.0f / (float)(ch * CHUNK + tid + 1);

    // Predecessor chunk partials: 4 groups x 64 channels, <=32 independent
    // L2-hot loads each, overlapping the in-flight x loads.
    {
        const int c   = tid & (C_ - 1);
        const int grp = tid >> 6;               // 0..3
        const float* gp = (const float*)g_part4;
        float ps = 0.f;
        for (int j = grp; j < ch; j += 4)
            ps += gp[(b * NCHUNK + j) * C_ + c];
        pred[grp][c] = ps;
    }

    // Register inclusive scan of the 4 rows.
    v1.x += v0.x; v1.y += v0.y; v1.z += v0.z; v1.w += v0.w;
    v2.x += v1.x; v2.y += v1.y; v2.z += v1.z; v2.w += v1.w;
    v3.x += v2.x; v3.y += v2.y; v3.z += v2.z; v3.w += v2.w;

    red[rl][cg] = v3;
    __syncthreads();

    // Combine the 4 predecessor groups.
    if (tid < C_)
        predt[tid] = (pred[0][tid] + pred[1][tid])
                   + (pred[2][tid] + pred[3][tid]);

    // Exclusive base across lower row lanes (<=15 shared loads, independent).
    float4 base = make_float4(0.f, 0.f, 0.f, 0.f);
    for (int r = 0; r < rl; r++) {
        float4 t4 = red[r][cg];
        base.x += t4.x; base.y += t4.y; base.z += t4.z; base.w += t4.w;
    }
    __syncthreads();

    {
        float4 pb = ((const float4*)predt)[cg];
        base.x += pb.x; base.y += pb.y; base.z += pb.z; base.w += pb.w;
    }

    const float* rp = &s_recip[rl * RPT];
    float4* __restrict__ yp = (float4*)(y + off);
    float4 o;
    #define EMIT(K, VK)                                        \
        { float r = rp[K];                                     \
          o.x = (VK.x + base.x) * r; o.y = (VK.y + base.y) * r;\
          o.z = (VK.z + base.z) * r; o.w = (VK.w + base.w) * r;\
          yp[K * (C_ / 4)] = o; }
    EMIT(0, v0) EMIT(1, v1) EMIT(2, v2) EMIT(3, v3)
    #undef EMIT
}

extern "C" void kernel_launch(void* const* d_in, const int* in_sizes, int n_in,
                              void* d_out, int out_size) {
    (void)in_sizes; (void)n_in; (void)out_size;
    const float* x = (const float*)d_in[0];   // [16, 8192, 64] fp32
    // d_in[1] (weights) is mathematically the causal 1/(i+1) matrix -> never read.
    float* y = (float*)d_out;

    k_partial<<<NBLK, NTHR>>>(x);
    k_scanout<<<NBLK, NTHR>>>(x, y);
}